// round 5
// baseline (speedup 1.0000x reference)
#include <cuda_runtime.h>
#include <cstdint>

#define Bn   16
#define Nn   512
#define Rn   10
#define DE   256
#define DR   64
#define DOUT 256
#define INDIM 3200
#define RELS  320

// Zt[br][o][m]  (tf32-RN-rounded fp32), 84MB scratch
__device__ float g_Z[(size_t)Bn * Rn * DOUT * Nn];

#define PAD 36
#define ATILE (128 * PAD)      // 4608 floats
#define BTILE (64 * PAD)       // 2304 floats
#define BSTRIDE 260            // k_z node tile row stride

#define KZ_SMEM ((64 * BSTRIDE + 2 * ATILE + Rn * 128) * 4)   // 108,544 B
#define KM_SMEM ((2 * ATILE + 2 * BTILE + 64) * 4)            //  55,552 B

__device__ __forceinline__ float rtf32(float x) {
    uint32_t r; asm("cvt.rna.tf32.f32 %0, %1;" : "=r"(r) : "f"(x));
    return __uint_as_float(r);
}

__device__ __forceinline__ void mma8(float* c, const uint32_t* a, const uint32_t* b) {
    asm volatile(
        "mma.sync.aligned.m16n8k8.row.col.f32.tf32.tf32.f32 "
        "{%0,%1,%2,%3}, {%4,%5,%6,%7}, {%8,%9}, {%0,%1,%2,%3};"
        : "+f"(c[0]), "+f"(c[1]), "+f"(c[2]), "+f"(c[3])
        : "r"(a[0]), "r"(a[1]), "r"(a[2]), "r"(a[3]), "r"(b[0]), "r"(b[1]));
}

// Warp tile 32(M) x 64(N).  A_chunk: [128 M rows][32 k] stride PAD (warp wm
// owns rows wm*32..+31).  B_chunk: [64 N rows][k] stride bs, pre-offset to the
// k-chunk.  4 warps per CTA, all share the full 64-wide N.
__device__ __forceinline__ void compute_chunk(const float* __restrict__ A_chunk,
                                              const float* __restrict__ B_chunk,
                                              int bs, int wm, int lane,
                                              float (&acc)[2][8][4]) {
    const float* a_base = A_chunk + (wm * 32) * PAD;
    const int r4 = lane >> 2, c4 = lane & 3;
#pragma unroll
    for (int ks = 0; ks < 4; ks++) {
        const int k = ks * 8 + c4;
        uint32_t af[2][4];
#pragma unroll
        for (int mi = 0; mi < 2; mi++) {
            const float* ap = a_base + (mi * 16 + r4) * PAD + k;
            af[mi][0] = __float_as_uint(ap[0]);
            af[mi][1] = __float_as_uint(ap[8 * PAD]);
            af[mi][2] = __float_as_uint(ap[4]);
            af[mi][3] = __float_as_uint(ap[8 * PAD + 4]);
        }
        uint32_t bf[8][2];
#pragma unroll
        for (int ni = 0; ni < 8; ni++) {
            const float* bp = B_chunk + (ni * 8 + r4) * bs + k;
            bf[ni][0] = __float_as_uint(bp[0]);
            bf[ni][1] = __float_as_uint(bp[4]);
        }
#pragma unroll
        for (int mi = 0; mi < 2; mi++)
#pragma unroll
            for (int ni = 0; ni < 8; ni++)
                mma8(acc[mi][ni], af[mi], bf[ni]);
    }
}

// ---------------------------------------------------------------------------
// k_z: CTA tile = o 128 (M) x m 64 (N), loops r internally; node tile (64 m x
// 256 d) SMEM-resident; W streams through a double buffer.
// Zt[br][o][m] = rtf32( (W_node_r @ node^T)[o][m] + v[r][o] )
// grid (8 m-tiles, 2 o-tiles, 16 b) = 256 CTAs, 128 threads.
// ---------------------------------------------------------------------------
__global__ __launch_bounds__(128) void k_z(const float* __restrict__ node,
                                           const float* __restrict__ rel,
                                           const float* __restrict__ W) {
    extern __shared__ float sm[];
    float* Bnode = sm;                       // 64 x BSTRIDE
    float* As    = sm + 64 * BSTRIDE;        // 2 x ATILE
    float* vs    = As + 2 * ATILE;           // [Rn][128]

    const int tid = threadIdx.x, lane = tid & 31, wm = tid >> 5;
    const int b = blockIdx.z;
    const int mm0 = blockIdx.x * 64;         // N-dim (m)
    const int o0  = blockIdx.y * 128;        // M-dim (o)

    // Stage node tile [64 m][256 d], tf32-RN rounded.
#pragma unroll 8
    for (int i = 0; i < 32; i++) {
        const int g = i * 128 + tid;
        const int row = g >> 6, c4 = g & 63;
        float4 v = *reinterpret_cast<const float4*>(
            node + ((size_t)(b * Nn + mm0 + row)) * DE + c4 * 4);
        v.x = rtf32(v.x); v.y = rtf32(v.y); v.z = rtf32(v.z); v.w = rtf32(v.w);
        *reinterpret_cast<float4*>(Bnode + row * BSTRIDE + c4 * 4) = v;
    }
    // v[r][o] = rel[b,r,:] . W[o, r*320+256 .. +64)
    for (int r = 0; r < Rn; r++) {
        const float* wr = W + (size_t)(o0 + tid) * INDIM + r * RELS + DE;
        const float* rp = rel + (size_t)(b * Rn + r) * DR;
        float s = 0.f;
#pragma unroll
        for (int d = 0; d < DR; d++) s += rp[d] * wr[d];
        vs[r * 128 + tid] = s;
    }

    float acc[2][8][4];
#pragma unroll
    for (int mi = 0; mi < 2; mi++)
#pragma unroll
        for (int ni = 0; ni < 8; ni++)
#pragma unroll
            for (int q = 0; q < 4; q++) acc[mi][ni][q] = 0.f;

    float4 va[8];
    auto ldgA = [&](int j) {                 // W tile: 128 o x 32 k
        const int r = j >> 3, kk = j & 7;
        const float* Ab = W + (size_t)o0 * INDIM + r * RELS + kk * 32;
#pragma unroll
        for (int i = 0; i < 8; i++) {
            const int idx = i * 128 + tid;
            va[i] = *reinterpret_cast<const float4*>(
                Ab + (size_t)(idx >> 3) * INDIM + (idx & 7) * 4);
        }
    };
    auto stsA = [&](int buf) {
        float* ad = As + buf * ATILE;
#pragma unroll
        for (int i = 0; i < 8; i++) {
            const int idx = i * 128 + tid;
            float4 a = va[i];
            a.x = rtf32(a.x); a.y = rtf32(a.y); a.z = rtf32(a.z); a.w = rtf32(a.w);
            *reinterpret_cast<float4*>(ad + (idx >> 3) * PAD + (idx & 7) * 4) = a;
        }
    };

    ldgA(0); stsA(0); __syncthreads();

    const int J = Rn * 8;                    // 80
    const int r4 = lane >> 2, c2 = 2 * (lane & 3);
    for (int j = 0; j < J; j++) {
        if (j + 1 < J) ldgA(j + 1);
        compute_chunk(As + (j & 1) * ATILE, Bnode + (j & 7) * 32,
                      BSTRIDE, wm, lane, acc);
        if ((j & 7) == 7) {                  // epilogue for relation r
            const int r = j >> 3;
            float* zr = g_Z + (size_t)(b * Rn + r) * (DOUT * Nn);
#pragma unroll
            for (int mi = 0; mi < 2; mi++) {
#pragma unroll
                for (int ni = 0; ni < 8; ni++) {
                    const int orow = wm * 32 + mi * 16 + r4;
                    const int mcol = ni * 8 + c2;
                    float* zp = zr + (size_t)(o0 + orow) * Nn + mm0 + mcol;
                    const float v0 = vs[r * 128 + orow];
                    float2 lo = { rtf32(acc[mi][ni][0] + v0),
                                  rtf32(acc[mi][ni][1] + v0) };
                    *reinterpret_cast<float2*>(zp) = lo;
                    const float v1 = vs[r * 128 + orow + 8];
                    float2 hi = { rtf32(acc[mi][ni][2] + v1),
                                  rtf32(acc[mi][ni][3] + v1) };
                    *reinterpret_cast<float2*>(zp + (size_t)8 * Nn) = hi;
#pragma unroll
                    for (int q = 0; q < 4; q++) acc[mi][ni][q] = 0.f;
                }
            }
        }
        __syncthreads();
        if (j + 1 < J) { stsA((j + 1) & 1); __syncthreads(); }
    }
}

// ---------------------------------------------------------------------------
// k_main: CTA tile = n 128 (M) x o 64 (N).  K = 5120 in 160 chunks.
// out[b][n][o] = bias[o] + sum_{r,m} adj[b,r,n,m] * Zt[br][o][m]
// grid (4 n-tiles, 4 o-tiles, 16 b) = 256 CTAs, 128 threads.
// ---------------------------------------------------------------------------
__global__ __launch_bounds__(128) void k_main(const float* __restrict__ adj,
                                              const float* __restrict__ bias,
                                              float* __restrict__ out) {
    extern __shared__ float sm[];
    float* As  = sm;                         // 2 x ATILE
    float* Bs  = sm + 2 * ATILE;             // 2 x BTILE
    float* bsm = Bs + 2 * BTILE;             // 64

    const int tid = threadIdx.x, lane = tid & 31, wm = tid >> 5;
    const int b = blockIdx.z;
    const int n0 = blockIdx.x * 128, o0 = blockIdx.y * 64;

    if (tid < 64) bsm[tid] = bias[o0 + tid];

    float acc[2][8][4];
#pragma unroll
    for (int mi = 0; mi < 2; mi++)
#pragma unroll
        for (int ni = 0; ni < 8; ni++)
#pragma unroll
            for (int q = 0; q < 4; q++) acc[mi][ni][q] = 0.f;

    float4 va[8], vb[4];
    auto ldg = [&](int j) {
        const int r = j >> 4, kk = j & 15;
        const float* Ab = adj + (size_t)(b * Rn + r) * (Nn * Nn)
                          + (size_t)n0 * Nn + kk * 32;                 // 128 n x 32 m
        const float* Bb = g_Z + (size_t)(b * Rn + r) * (DOUT * Nn)
                          + (size_t)o0 * Nn + kk * 32;                 // 64 o x 32 m
#pragma unroll
        for (int i = 0; i < 8; i++) {
            const int idx = i * 128 + tid;
            va[i] = *reinterpret_cast<const float4*>(
                Ab + (size_t)(idx >> 3) * Nn + (idx & 7) * 4);
        }
#pragma unroll
        for (int i = 0; i < 4; i++) {
            const int idx = i * 128 + tid;
            vb[i] = *reinterpret_cast<const float4*>(
                Bb + (size_t)(idx >> 3) * Nn + (idx & 7) * 4);
        }
    };
    auto sts = [&](int buf) {
        float* ad = As + buf * ATILE;
        float* bd = Bs + buf * BTILE;
#pragma unroll
        for (int i = 0; i < 8; i++) {
            const int idx = i * 128 + tid;
            float4 a = va[i];
            a.x = rtf32(a.x); a.y = rtf32(a.y); a.z = rtf32(a.z); a.w = rtf32(a.w);
            *reinterpret_cast<float4*>(ad + (idx >> 3) * PAD + (idx & 7) * 4) = a;
        }
#pragma unroll
        for (int i = 0; i < 4; i++) {
            const int idx = i * 128 + tid;
            *reinterpret_cast<float4*>(bd + (idx >> 3) * PAD + (idx & 7) * 4) = vb[i];
        }
    };

    ldg(0); sts(0); __syncthreads();

    const int J = 160;
    for (int j = 0; j < J; j++) {
        if (j + 1 < J) ldg(j + 1);
        compute_chunk(As + (j & 1) * ATILE, Bs + (j & 1) * BTILE,
                      PAD, wm, lane, acc);
        __syncthreads();
        if (j + 1 < J) { sts((j + 1) & 1); __syncthreads(); }
    }

    const int r4 = lane >> 2, c2 = 2 * (lane & 3);
#pragma unroll
    for (int mi = 0; mi < 2; mi++) {
#pragma unroll
        for (int ni = 0; ni < 8; ni++) {
            const int nrow = wm * 32 + mi * 16 + r4;
            const int ocol = ni * 8 + c2;
            float* op = out + ((size_t)(b * Nn + n0 + nrow)) * DOUT + o0 + ocol;
            float2 lo = { acc[mi][ni][0] + bsm[ocol], acc[mi][ni][1] + bsm[ocol + 1] };
            *reinterpret_cast<float2*>(op) = lo;
            float2 hi = { acc[mi][ni][2] + bsm[ocol], acc[mi][ni][3] + bsm[ocol + 1] };
            *reinterpret_cast<float2*>(op + (size_t)8 * DOUT) = hi;
        }
    }
}

// ---------------------------------------------------------------------------
extern "C" void kernel_launch(void* const* d_in, const int* in_sizes, int n_in,
                              void* d_out, int out_size) {
    const float *node = nullptr, *rel = nullptr, *adj = nullptr,
                *W = nullptr, *bias = nullptr;
    for (int i = 0; i < n_in; i++) {
        const int s = in_sizes[i];
        if      (s == Bn * Nn * DE)      node = (const float*)d_in[i];
        else if (s == Bn * Rn * DR)      rel  = (const float*)d_in[i];
        else if (s == Bn * Rn * Nn * Nn) adj  = (const float*)d_in[i];
        else if (s == DOUT * INDIM)      W    = (const float*)d_in[i];
        else if (s == DOUT)              bias = (const float*)d_in[i];
    }
    cudaFuncSetAttribute(k_z,    cudaFuncAttributeMaxDynamicSharedMemorySize, KZ_SMEM);
    cudaFuncSetAttribute(k_main, cudaFuncAttributeMaxDynamicSharedMemorySize, KM_SMEM);

    k_z   <<<dim3(8, 2, Bn), 128, KZ_SMEM>>>(node, rel, W);
    k_main<<<dim3(4, 4, Bn), 128, KM_SMEM>>>(adj, bias, (float*)d_out);
}

// round 6
// speedup vs baseline: 1.6393x; 1.6393x over previous
#include <cuda_runtime.h>
#include <cuda_bf16.h>
#include <cstdint>

#define Bn   16
#define Nn   512
#define Rn   10
#define DE   256
#define DR   64
#define DOUT 256
#define INDIM 3200
#define RELS  320

// bf16 scratch
__device__ __align__(16) __nv_bfloat16 g_A [(size_t)Bn * Rn * Nn * Nn];    // adj bf16, 84MB
__device__ __align__(16) __nv_bfloat16 g_Zb[(size_t)Bn * Rn * DOUT * Nn]; // Zt bf16, 42MB
__device__ __align__(16) __nv_bfloat16 g_N [(size_t)Bn * Nn * DE];        // node bf16
__device__ __align__(16) __nv_bfloat16 g_W [(size_t)DOUT * INDIM];        // W bf16
__device__ float g_V[Bn * Rn * DOUT];                                     // v fp32

#define RS 40                    // smem row stride in halves (80 bytes)
#define TILE_B  (128 * RS * 2)   // 10240 bytes per operand tile
#define STAGE_B (2 * TILE_B)     // 20480 bytes (A + B)
#define KM_SMEM (4 * STAGE_B + 512)
#define KZ_SMEM (4 * STAGE_B + Rn * 128 * 4)

__device__ __forceinline__ uint32_t smem_u32(const void* p) {
    uint32_t a;
    asm("{ .reg .u64 t; cvta.to.shared.u64 t, %1; cvt.u32.u64 %0, t; }"
        : "=r"(a) : "l"(p));
    return a;
}

#define CP_ASYNC16(dst_u32, src) \
    asm volatile("cp.async.cg.shared.global [%0], [%1], 16;" \
                 :: "r"(dst_u32), "l"(src) : "memory")
#define CP_COMMIT() asm volatile("cp.async.commit_group;" ::: "memory")
#define CP_WAIT2()  asm volatile("cp.async.wait_group 2;" ::: "memory")

#define LDMX4(r0, r1, r2, r3, addr) \
    asm volatile("ldmatrix.sync.aligned.m8n8.x4.shared.b16 {%0,%1,%2,%3}, [%4];" \
                 : "=r"(r0), "=r"(r1), "=r"(r2), "=r"(r3) : "r"(addr))

__device__ __forceinline__ void mma16(float* c, const uint32_t* a,
                                      uint32_t b0, uint32_t b1) {
    asm volatile(
        "mma.sync.aligned.m16n8k16.row.col.f32.bf16.bf16.f32 "
        "{%0,%1,%2,%3}, {%4,%5,%6,%7}, {%8,%9}, {%0,%1,%2,%3};"
        : "+f"(c[0]), "+f"(c[1]), "+f"(c[2]), "+f"(c[3])
        : "r"(a[0]), "r"(a[1]), "r"(a[2]), "r"(a[3]), "r"(b0), "r"(b1));
}

// One k=32 chunk: warp tile 32(M) x 64(N). A tile at stage base, B at +TILE_B.
__device__ __forceinline__ void compute_chunk(uint32_t st,
                                              const uint32_t (&aoff)[2][2],
                                              const uint32_t (&boff)[4][2],
                                              float (&acc)[2][8][4]) {
    uint32_t a[2][2][4], bq[4][2][4];
#pragma unroll
    for (int mi = 0; mi < 2; mi++)
#pragma unroll
        for (int kk = 0; kk < 2; kk++)
            LDMX4(a[mi][kk][0], a[mi][kk][1], a[mi][kk][2], a[mi][kk][3],
                  st + aoff[mi][kk]);
#pragma unroll
    for (int nb = 0; nb < 4; nb++)
#pragma unroll
        for (int kk = 0; kk < 2; kk++)
            LDMX4(bq[nb][kk][0], bq[nb][kk][1], bq[nb][kk][2], bq[nb][kk][3],
                  st + boff[nb][kk]);
#pragma unroll
    for (int kk = 0; kk < 2; kk++)
#pragma unroll
        for (int mi = 0; mi < 2; mi++)
#pragma unroll
            for (int ni = 0; ni < 8; ni++) {
                const int nb = ni >> 1, odd = ni & 1;
                mma16(acc[mi][ni], a[mi][kk], bq[nb][kk][odd], bq[nb][kk][2 + odd]);
            }
}

// ---------------------------------------------------------------------------
// k_conv: adj/node/W -> bf16 scratch; blocks 0..159 also compute v[b][r][o].
// ---------------------------------------------------------------------------
__global__ void k_conv(const float* __restrict__ adj, const float* __restrict__ node,
                       const float* __restrict__ W, const float* __restrict__ rel) {
    const size_t stride = (size_t)gridDim.x * blockDim.x;
    const size_t t0 = (size_t)blockIdx.x * blockDim.x + threadIdx.x;

    const size_t nadj = (size_t)Bn * Rn * Nn * Nn / 4;
    for (size_t i = t0; i < nadj; i += stride) {
        float4 v = reinterpret_cast<const float4*>(adj)[i];
        __nv_bfloat162 p0 = __floats2bfloat162_rn(v.x, v.y);
        __nv_bfloat162 p1 = __floats2bfloat162_rn(v.z, v.w);
        uint2 u = { *reinterpret_cast<unsigned*>(&p0), *reinterpret_cast<unsigned*>(&p1) };
        reinterpret_cast<uint2*>(g_A)[i] = u;
    }
    const size_t nnode = (size_t)Bn * Nn * DE / 4;
    for (size_t i = t0; i < nnode; i += stride) {
        float4 v = reinterpret_cast<const float4*>(node)[i];
        __nv_bfloat162 p0 = __floats2bfloat162_rn(v.x, v.y);
        __nv_bfloat162 p1 = __floats2bfloat162_rn(v.z, v.w);
        uint2 u = { *reinterpret_cast<unsigned*>(&p0), *reinterpret_cast<unsigned*>(&p1) };
        reinterpret_cast<uint2*>(g_N)[i] = u;
    }
    const size_t nw = (size_t)DOUT * INDIM / 4;
    for (size_t i = t0; i < nw; i += stride) {
        float4 v = reinterpret_cast<const float4*>(W)[i];
        __nv_bfloat162 p0 = __floats2bfloat162_rn(v.x, v.y);
        __nv_bfloat162 p1 = __floats2bfloat162_rn(v.z, v.w);
        uint2 u = { *reinterpret_cast<unsigned*>(&p0), *reinterpret_cast<unsigned*>(&p1) };
        reinterpret_cast<uint2*>(g_W)[i] = u;
    }
    // v[b][r][o] = rel[b,r,:] . W[o, r*320+256 .. +64)  (fp32)
    if (blockIdx.x < Bn * Rn) {
        const int br = blockIdx.x, r = br % Rn;
        const int o = threadIdx.x;               // 256 threads
        const float* wr = W + (size_t)o * INDIM + r * RELS + DE;
        const float* rp = rel + (size_t)br * DR;
        float s = 0.f;
#pragma unroll
        for (int d = 0; d < DR; d++) s += rp[d] * wr[d];
        g_V[br * DOUT + o] = s;
    }
}

// ---------------------------------------------------------------------------
// k_z: CTA tile o 128 (M) x m 128 (N); r-loop; K=256 per r in 8 chunks.
// Zt[br][o][m] = bf16( (W_r @ node^T)[o][m] + v[r][o] )
// grid (4 m, 2 o, 16 b), 256 threads.
// ---------------------------------------------------------------------------
__global__ __launch_bounds__(256, 1) void k_z() {
    extern __shared__ __align__(16) char smc[];
    const uint32_t sb = smem_u32(smc);
    float* vs = reinterpret_cast<float*>(smc + 4 * STAGE_B);   // [Rn][128]

    const int tid = threadIdx.x, lane = tid & 31, warp = tid >> 5;
    const int wm = warp & 3, wn = warp >> 2;
    const int b = blockIdx.z;
    const int mm0 = blockIdx.x * 128;   // N (m)
    const int o0  = blockIdx.y * 128;   // M (o)

    // stage v[r][o-tile] into smem (coalesced)
#pragma unroll
    for (int i = 0; i < 5; i++) {
        const int idx = i * 256 + tid;
        const int r = idx >> 7, o = idx & 127;
        vs[idx] = g_V[(b * Rn + r) * DOUT + o0 + o];
    }

    const int t8 = lane >> 3;
    const int rIn = (t8 & 1) * 8 + (lane & 7), kIn = (t8 >> 1) * 8;
    uint32_t aoff[2][2], boff[4][2];
#pragma unroll
    for (int mi = 0; mi < 2; mi++)
#pragma unroll
        for (int kk = 0; kk < 2; kk++)
            aoff[mi][kk] = ((wm * 32 + mi * 16 + rIn) * RS + kk * 16 + kIn) * 2;
#pragma unroll
    for (int nb = 0; nb < 4; nb++)
#pragma unroll
        for (int kk = 0; kk < 2; kk++)
            boff[nb][kk] = TILE_B + ((wn * 64 + nb * 16 + rIn) * RS + kk * 16 + kIn) * 2;

    float acc[2][8][4];
#pragma unroll
    for (int mi = 0; mi < 2; mi++)
#pragma unroll
        for (int ni = 0; ni < 8; ni++)
#pragma unroll
            for (int q = 0; q < 4; q++) acc[mi][ni][q] = 0.f;

    auto cpchunk = [&](int j) {
        const int rj = j >> 3, kk = j & 7;
        const __nv_bfloat16* Ag = g_W + (size_t)o0 * INDIM + rj * RELS + kk * 32;
        const __nv_bfloat16* Bg = g_N + (size_t)(b * Nn + mm0) * DE + kk * 32;
        const uint32_t st = sb + (j & 3) * STAGE_B;
#pragma unroll
        for (int q = 0; q < 2; q++) {
            const int idx = q * 256 + tid, r = idx >> 2, s = idx & 3;
            CP_ASYNC16(st + (r * RS + s * 8) * 2, Ag + (size_t)r * INDIM + s * 8);
            CP_ASYNC16(st + TILE_B + (r * RS + s * 8) * 2, Bg + (size_t)r * DE + s * 8);
        }
    };

    cpchunk(0); CP_COMMIT(); cpchunk(1); CP_COMMIT();

    const int J = Rn * 8;   // 80
    const int r4 = lane >> 2, c2 = 2 * (lane & 3);
    for (int j = 0; j < J; j++) {
        if (j + 2 < J) cpchunk(j + 2);
        CP_COMMIT();
        CP_WAIT2();
        __syncthreads();
        compute_chunk(sb + (j & 3) * STAGE_B, aoff, boff, acc);
        if ((j & 7) == 7) {
            const int r = j >> 3;
            __nv_bfloat16* zr = g_Zb + (size_t)(b * Rn + r) * (DOUT * Nn);
#pragma unroll
            for (int mi = 0; mi < 2; mi++) {
#pragma unroll
                for (int ni = 0; ni < 8; ni++) {
                    const int orow = wm * 32 + mi * 16 + r4;
                    const int mcol = wn * 64 + ni * 8 + c2;
                    __nv_bfloat16* zp = zr + (size_t)(o0 + orow) * Nn + mm0 + mcol;
                    const float v0 = vs[r * 128 + orow];
                    __nv_bfloat162 lo = __floats2bfloat162_rn(acc[mi][ni][0] + v0,
                                                              acc[mi][ni][1] + v0);
                    *reinterpret_cast<__nv_bfloat162*>(zp) = lo;
                    const float v1 = vs[r * 128 + orow + 8];
                    __nv_bfloat162 hi = __floats2bfloat162_rn(acc[mi][ni][2] + v1,
                                                              acc[mi][ni][3] + v1);
                    *reinterpret_cast<__nv_bfloat162*>(zp + (size_t)8 * Nn) = hi;
#pragma unroll
                    for (int q = 0; q < 4; q++) acc[mi][ni][q] = 0.f;
                }
            }
        }
    }
}

// ---------------------------------------------------------------------------
// k_main: CTA tile n 128 (M) x o 128 (N); K = 5120 in 160 chunks.
// out[b][n][o] = bias[o] + sum_{r,m} adjb[b,r,n,m] * Zt[br][o][m]
// grid (4 n, 2 o, 16 b), 256 threads.
// ---------------------------------------------------------------------------
__global__ __launch_bounds__(256, 1) void k_main(const float* __restrict__ bias,
                                                 float* __restrict__ out) {
    extern __shared__ __align__(16) char smc[];
    const uint32_t sb = smem_u32(smc);
    float* bsm = reinterpret_cast<float*>(smc + 4 * STAGE_B);   // 128

    const int tid = threadIdx.x, lane = tid & 31, warp = tid >> 5;
    const int wm = warp & 3, wn = warp >> 2;
    const int b = blockIdx.z;
    const int n0 = blockIdx.x * 128, o0 = blockIdx.y * 128;

    if (tid < 128) bsm[tid] = bias[o0 + tid];

    const int t8 = lane >> 3;
    const int rIn = (t8 & 1) * 8 + (lane & 7), kIn = (t8 >> 1) * 8;
    uint32_t aoff[2][2], boff[4][2];
#pragma unroll
    for (int mi = 0; mi < 2; mi++)
#pragma unroll
        for (int kk = 0; kk < 2; kk++)
            aoff[mi][kk] = ((wm * 32 + mi * 16 + rIn) * RS + kk * 16 + kIn) * 2;
#pragma unroll
    for (int nb = 0; nb < 4; nb++)
#pragma unroll
        for (int kk = 0; kk < 2; kk++)
            boff[nb][kk] = TILE_B + ((wn * 64 + nb * 16 + rIn) * RS + kk * 16 + kIn) * 2;

    float acc[2][8][4];
#pragma unroll
    for (int mi = 0; mi < 2; mi++)
#pragma unroll
        for (int ni = 0; ni < 8; ni++)
#pragma unroll
            for (int q = 0; q < 4; q++) acc[mi][ni][q] = 0.f;

    auto cpchunk = [&](int j) {
        const int rj = j >> 4, kk = j & 15;
        const __nv_bfloat16* Ag = g_A + ((size_t)(b * Rn + rj) * Nn + n0) * Nn + kk * 32;
        const __nv_bfloat16* Bg = g_Zb + ((size_t)(b * Rn + rj) * DOUT + o0) * Nn + kk * 32;
        const uint32_t st = sb + (j & 3) * STAGE_B;
#pragma unroll
        for (int q = 0; q < 2; q++) {
            const int idx = q * 256 + tid, r = idx >> 2, s = idx & 3;
            CP_ASYNC16(st + (r * RS + s * 8) * 2, Ag + (size_t)r * Nn + s * 8);
            CP_ASYNC16(st + TILE_B + (r * RS + s * 8) * 2, Bg + (size_t)r * Nn + s * 8);
        }
    };

    cpchunk(0); CP_COMMIT(); cpchunk(1); CP_COMMIT();

    const int J = 160;
    for (int j = 0; j < J; j++) {
        if (j + 2 < J) cpchunk(j + 2);
        CP_COMMIT();
        CP_WAIT2();
        __syncthreads();
        compute_chunk(sb + (j & 3) * STAGE_B, aoff, boff, acc);
    }

    const int r4 = lane >> 2, c2 = 2 * (lane & 3);
#pragma unroll
    for (int mi = 0; mi < 2; mi++) {
#pragma unroll
        for (int ni = 0; ni < 8; ni++) {
            const int nrow = wm * 32 + mi * 16 + r4;
            const int ocol = wn * 64 + ni * 8 + c2;
            float* op = out + ((size_t)(b * Nn + n0 + nrow)) * DOUT + o0 + ocol;
            float2 lo = { acc[mi][ni][0] + bsm[ocol], acc[mi][ni][1] + bsm[ocol + 1] };
            *reinterpret_cast<float2*>(op) = lo;
            float2 hi = { acc[mi][ni][2] + bsm[ocol], acc[mi][ni][3] + bsm[ocol + 1] };
            *reinterpret_cast<float2*>(op + (size_t)8 * DOUT) = hi;
        }
    }
}

// ---------------------------------------------------------------------------
extern "C" void kernel_launch(void* const* d_in, const int* in_sizes, int n_in,
                              void* d_out, int out_size) {
    const float *node = nullptr, *rel = nullptr, *adj = nullptr,
                *W = nullptr, *bias = nullptr;
    for (int i = 0; i < n_in; i++) {
        const int s = in_sizes[i];
        if      (s == Bn * Nn * DE)      node = (const float*)d_in[i];
        else if (s == Bn * Rn * DR)      rel  = (const float*)d_in[i];
        else if (s == Bn * Rn * Nn * Nn) adj  = (const float*)d_in[i];
        else if (s == DOUT * INDIM)      W    = (const float*)d_in[i];
        else if (s == DOUT)              bias = (const float*)d_in[i];
    }
    cudaFuncSetAttribute(k_z,    cudaFuncAttributeMaxDynamicSharedMemorySize, KZ_SMEM);
    cudaFuncSetAttribute(k_main, cudaFuncAttributeMaxDynamicSharedMemorySize, KM_SMEM);

    k_conv<<<1024, 256>>>(adj, node, W, rel);
    k_z   <<<dim3(4, 2, Bn), 256, KZ_SMEM>>>();
    k_main<<<dim3(4, 2, Bn), 256, KM_SMEM>>>(bias, (float*)d_out);
}

// round 7
// speedup vs baseline: 1.6779x; 1.0236x over previous
#include <cuda_runtime.h>
#include <cuda_bf16.h>
#include <cstdint>

#define Bn   16
#define Nn   512
#define Rn   10
#define DE   256
#define DR   64
#define DOUT 256
#define INDIM 3200
#define RELS  320

// bf16 scratch
__device__ __align__(16) __nv_bfloat16 g_A [(size_t)Bn * Rn * Nn * Nn];   // adj bf16
__device__ __align__(16) __nv_bfloat16 g_Zb[(size_t)Bn * Rn * DOUT * Nn]; // Zt bf16
__device__ __align__(16) __nv_bfloat16 g_N [(size_t)Bn * Nn * DE];        // node bf16
__device__ __align__(16) __nv_bfloat16 g_W [(size_t)DOUT * INDIM];        // W bf16
__device__ float g_V[Bn * Rn * DOUT];                                     // v fp32

// ---- k_zc (fused Z-GEMM + adj conversion): k=32 stages, RS=40 halves ----
#define RSZ 40
#define TILE_Z  (128 * RSZ * 2)     // 10240 B / operand
#define STAGE_Z (2 * TILE_Z)        // 20480 B
#define KZ_SMEM (3 * STAGE_Z + Rn * 128 * 4)   // 66560 B
#define GEMMB 128
#define CONVB 320

// ---- k_main: k=64 stages, RS=72 halves ----
#define RSM 72
#define TILE_M  (128 * RSM * 2)     // 18432 B / operand
#define STAGE_M (2 * TILE_M)        // 36864 B
#define KM_SMEM (3 * STAGE_M + 512) // 111104 B

__device__ __forceinline__ uint32_t smem_u32(const void* p) {
    uint32_t a;
    asm("{ .reg .u64 t; cvta.to.shared.u64 t, %1; cvt.u32.u64 %0, t; }"
        : "=r"(a) : "l"(p));
    return a;
}

#define CP_ASYNC16(dst_u32, src) \
    asm volatile("cp.async.cg.shared.global [%0], [%1], 16;" \
                 :: "r"(dst_u32), "l"(src) : "memory")
#define CP_COMMIT() asm volatile("cp.async.commit_group;" ::: "memory")
#define CP_WAIT1()  asm volatile("cp.async.wait_group 1;" ::: "memory")

#define LDMX4(r0, r1, r2, r3, addr) \
    asm volatile("ldmatrix.sync.aligned.m8n8.x4.shared.b16 {%0,%1,%2,%3}, [%4];" \
                 : "=r"(r0), "=r"(r1), "=r"(r2), "=r"(r3) : "r"(addr))

__device__ __forceinline__ void mma16(float* c, const uint32_t* a,
                                      uint32_t b0, uint32_t b1) {
    asm volatile(
        "mma.sync.aligned.m16n8k16.row.col.f32.bf16.bf16.f32 "
        "{%0,%1,%2,%3}, {%4,%5,%6,%7}, {%8,%9}, {%0,%1,%2,%3};"
        : "+f"(c[0]), "+f"(c[1]), "+f"(c[2]), "+f"(c[3])
        : "r"(a[0]), "r"(a[1]), "r"(a[2]), "r"(a[3]), "r"(b0), "r"(b1));
}

// One k=32 sub-chunk, warp tile 32(M) x 64(N). A at st, B at st + tileB.
__device__ __forceinline__ void compute32(uint32_t st,
                                          const uint32_t (&aoff)[2][2],
                                          const uint32_t (&boff)[4][2],
                                          float (&acc)[2][8][4]) {
    uint32_t a[2][2][4], bq[4][2][4];
#pragma unroll
    for (int mi = 0; mi < 2; mi++)
#pragma unroll
        for (int kk = 0; kk < 2; kk++)
            LDMX4(a[mi][kk][0], a[mi][kk][1], a[mi][kk][2], a[mi][kk][3],
                  st + aoff[mi][kk]);
#pragma unroll
    for (int nb = 0; nb < 4; nb++)
#pragma unroll
        for (int kk = 0; kk < 2; kk++)
            LDMX4(bq[nb][kk][0], bq[nb][kk][1], bq[nb][kk][2], bq[nb][kk][3],
                  st + boff[nb][kk]);
#pragma unroll
    for (int kk = 0; kk < 2; kk++)
#pragma unroll
        for (int mi = 0; mi < 2; mi++)
#pragma unroll
            for (int ni = 0; ni < 8; ni++) {
                const int nb = ni >> 1, odd = ni & 1;
                mma16(acc[mi][ni], a[mi][kk], bq[nb][kk][odd], bq[nb][kk][2 + odd]);
            }
}

// ---------------------------------------------------------------------------
// k_pre: node/W -> bf16, v[b][r][o] (fp32).  grid 160 x 256.
// ---------------------------------------------------------------------------
__global__ void k_pre(const float* __restrict__ node, const float* __restrict__ W,
                      const float* __restrict__ rel) {
    const size_t stride = (size_t)gridDim.x * blockDim.x;
    const size_t t0 = (size_t)blockIdx.x * blockDim.x + threadIdx.x;

    const size_t nnode = (size_t)Bn * Nn * DE / 4;
    for (size_t i = t0; i < nnode; i += stride) {
        float4 v = reinterpret_cast<const float4*>(node)[i];
        __nv_bfloat162 p0 = __floats2bfloat162_rn(v.x, v.y);
        __nv_bfloat162 p1 = __floats2bfloat162_rn(v.z, v.w);
        uint2 u = { *reinterpret_cast<unsigned*>(&p0), *reinterpret_cast<unsigned*>(&p1) };
        reinterpret_cast<uint2*>(g_N)[i] = u;
    }
    const size_t nw = (size_t)DOUT * INDIM / 4;
    for (size_t i = t0; i < nw; i += stride) {
        float4 v = reinterpret_cast<const float4*>(W)[i];
        __nv_bfloat162 p0 = __floats2bfloat162_rn(v.x, v.y);
        __nv_bfloat162 p1 = __floats2bfloat162_rn(v.z, v.w);
        uint2 u = { *reinterpret_cast<unsigned*>(&p0), *reinterpret_cast<unsigned*>(&p1) };
        reinterpret_cast<uint2*>(g_W)[i] = u;
    }
    if (blockIdx.x < Bn * Rn) {
        const int br = blockIdx.x, r = br % Rn;
        const int o = threadIdx.x;          // 256 threads
        const float* wr = W + (size_t)o * INDIM + r * RELS + DE;
        const float* rp = rel + (size_t)br * DR;
        float s = 0.f;
#pragma unroll
        for (int d = 0; d < DR; d++) s += rp[d] * wr[d];
        g_V[br * DOUT + o] = s;
    }
}

// ---------------------------------------------------------------------------
// k_zc: blocks [0,128): Z GEMM; blocks [128,448): adj fp32 -> bf16 stream.
// Z GEMM: CTA tile o 128 (M) x m 128 (N); r-loop; 8 chunks of k=32 per r.
// ---------------------------------------------------------------------------
__global__ __launch_bounds__(256, 2) void k_zc(const float* __restrict__ adj) {
    const int tid = threadIdx.x;

    if (blockIdx.x >= GEMMB) {
        // ---- adj conversion ----
        const size_t stride = (size_t)CONVB * 256;
        const size_t nq = (size_t)Bn * Rn * Nn * Nn / 4;
        for (size_t i = (size_t)(blockIdx.x - GEMMB) * 256 + tid; i < nq; i += stride) {
            float4 v = reinterpret_cast<const float4*>(adj)[i];
            __nv_bfloat162 p0 = __floats2bfloat162_rn(v.x, v.y);
            __nv_bfloat162 p1 = __floats2bfloat162_rn(v.z, v.w);
            uint2 u = { *reinterpret_cast<unsigned*>(&p0), *reinterpret_cast<unsigned*>(&p1) };
            reinterpret_cast<uint2*>(g_A)[i] = u;
        }
        return;
    }

    // ---- Z GEMM ----
    extern __shared__ __align__(16) char smc[];
    const uint32_t sb = smem_u32(smc);
    float* vs = reinterpret_cast<float*>(smc + 3 * STAGE_Z);   // [Rn][128]

    const int lane = tid & 31, warp = tid >> 5;
    const int wm = warp & 3, wn = warp >> 2;
    const int bid = blockIdx.x;
    const int b = bid >> 3, tt = bid & 7;
    const int mm0 = (tt & 3) * 128;     // N (m)
    const int o0  = (tt >> 2) * 128;    // M (o)

#pragma unroll
    for (int i = 0; i < 5; i++) {
        const int idx = i * 256 + tid;
        vs[idx] = g_V[(b * Rn + (idx >> 7)) * DOUT + o0 + (idx & 127)];
    }

    const int t8 = lane >> 3;
    const int rIn = (t8 & 1) * 8 + (lane & 7), kIn = (t8 >> 1) * 8;
    uint32_t aoff[2][2], boff[4][2];
#pragma unroll
    for (int mi = 0; mi < 2; mi++)
#pragma unroll
        for (int kk = 0; kk < 2; kk++)
            aoff[mi][kk] = ((wm * 32 + mi * 16 + rIn) * RSZ + kk * 16 + kIn) * 2;
#pragma unroll
    for (int nb = 0; nb < 4; nb++)
#pragma unroll
        for (int kk = 0; kk < 2; kk++)
            boff[nb][kk] = TILE_Z + ((wn * 64 + nb * 16 + rIn) * RSZ + kk * 16 + kIn) * 2;

    float acc[2][8][4];
#pragma unroll
    for (int mi = 0; mi < 2; mi++)
#pragma unroll
        for (int ni = 0; ni < 8; ni++)
#pragma unroll
            for (int q = 0; q < 4; q++) acc[mi][ni][q] = 0.f;

    auto cpchunk = [&](int j) {
        const int rj = j >> 3, kk = j & 7;
        const __nv_bfloat16* Ag = g_W + (size_t)o0 * INDIM + rj * RELS + kk * 32;
        const __nv_bfloat16* Bg = g_N + (size_t)(b * Nn + mm0) * DE + kk * 32;
        const uint32_t st = sb + (j % 3) * STAGE_Z;
#pragma unroll
        for (int q = 0; q < 2; q++) {
            const int idx = q * 256 + tid, r = idx >> 2, s = idx & 3;
            CP_ASYNC16(st + (r * RSZ + s * 8) * 2, Ag + (size_t)r * INDIM + s * 8);
            CP_ASYNC16(st + TILE_Z + (r * RSZ + s * 8) * 2, Bg + (size_t)r * DE + s * 8);
        }
    };

    cpchunk(0); CP_COMMIT();
    cpchunk(1); CP_COMMIT();

    const int J = Rn * 8;   // 80
    const int r4 = lane >> 2, c2 = 2 * (lane & 3);
    for (int j = 0; j < J; j++) {
        CP_WAIT1();                       // group j complete (j+1 in flight)
        __syncthreads();                  // all threads past compute(j-1)
        if (j + 2 < J) cpchunk(j + 2);
        CP_COMMIT();                      // uniform (possibly empty) commit
        compute32(sb + (j % 3) * STAGE_Z, aoff, boff, acc);
        if ((j & 7) == 7) {
            const int r = j >> 3;
            __nv_bfloat16* zr = g_Zb + (size_t)(b * Rn + r) * (DOUT * Nn);
#pragma unroll
            for (int mi = 0; mi < 2; mi++) {
#pragma unroll
                for (int ni = 0; ni < 8; ni++) {
                    const int orow = wm * 32 + mi * 16 + r4;
                    const int mcol = wn * 64 + ni * 8 + c2;
                    __nv_bfloat16* zp = zr + (size_t)(o0 + orow) * Nn + mm0 + mcol;
                    const float v0 = vs[r * 128 + orow];
                    __nv_bfloat162 lo = __floats2bfloat162_rn(acc[mi][ni][0] + v0,
                                                              acc[mi][ni][1] + v0);
                    *reinterpret_cast<__nv_bfloat162*>(zp) = lo;
                    const float v1 = vs[r * 128 + orow + 8];
                    __nv_bfloat162 hi = __floats2bfloat162_rn(acc[mi][ni][2] + v1,
                                                              acc[mi][ni][3] + v1);
                    *reinterpret_cast<__nv_bfloat162*>(zp + (size_t)8 * Nn) = hi;
#pragma unroll
                    for (int q = 0; q < 4; q++) acc[mi][ni][q] = 0.f;
                }
            }
        }
    }
}

// ---------------------------------------------------------------------------
// k_main: CTA tile n 128 (M) x o 128 (N); K = 5120 in 80 stages of k=64.
// out[b][n][o] = bias[o] + sum_{r,m} adjb[b,r,n,m] * Zt[br][o][m]
// grid (4 n, 2 o, 16 b), 256 threads.
// ---------------------------------------------------------------------------
__global__ __launch_bounds__(256, 1) void k_main(const float* __restrict__ bias,
                                                 float* __restrict__ out) {
    extern __shared__ __align__(16) char smc[];
    const uint32_t sb = smem_u32(smc);
    float* bsm = reinterpret_cast<float*>(smc + 3 * STAGE_M);   // 128

    const int tid = threadIdx.x, lane = tid & 31, warp = tid >> 5;
    const int wm = warp & 3, wn = warp >> 2;
    const int b = blockIdx.z;
    const int n0 = blockIdx.x * 128, o0 = blockIdx.y * 128;

    if (tid < 128) bsm[tid] = bias[o0 + tid];

    const int t8 = lane >> 3;
    const int rIn = (t8 & 1) * 8 + (lane & 7), kIn = (t8 >> 1) * 8;
    uint32_t aoff[2][2], boff[4][2];
#pragma unroll
    for (int mi = 0; mi < 2; mi++)
#pragma unroll
        for (int kk = 0; kk < 2; kk++)
            aoff[mi][kk] = ((wm * 32 + mi * 16 + rIn) * RSM + kk * 16 + kIn) * 2;
#pragma unroll
    for (int nb = 0; nb < 4; nb++)
#pragma unroll
        for (int kk = 0; kk < 2; kk++)
            boff[nb][kk] = TILE_M + ((wn * 64 + nb * 16 + rIn) * RSM + kk * 16 + kIn) * 2;

    float acc[2][8][4];
#pragma unroll
    for (int mi = 0; mi < 2; mi++)
#pragma unroll
        for (int ni = 0; ni < 8; ni++)
#pragma unroll
            for (int q = 0; q < 4; q++) acc[mi][ni][q] = 0.f;

    auto cpchunk = [&](int j) {           // stage = k=64 slab: r = j>>3, kk = j&7
        const int rj = j >> 3, kk = j & 7;
        const __nv_bfloat16* Ag = g_A + ((size_t)(b * Rn + rj) * Nn + n0) * Nn + kk * 64;
        const __nv_bfloat16* Bg = g_Zb + ((size_t)(b * Rn + rj) * DOUT + o0) * Nn + kk * 64;
        const uint32_t st = sb + (j % 3) * STAGE_M;
#pragma unroll
        for (int q = 0; q < 4; q++) {
            const int idx = q * 256 + tid, r = idx >> 3, s = idx & 7;
            CP_ASYNC16(st + (r * RSM + s * 8) * 2, Ag + (size_t)r * Nn + s * 8);
            CP_ASYNC16(st + TILE_M + (r * RSM + s * 8) * 2, Bg + (size_t)r * Nn + s * 8);
        }
    };

    cpchunk(0); CP_COMMIT();
    cpchunk(1); CP_COMMIT();

    const int J = 80;
    for (int j = 0; j < J; j++) {
        CP_WAIT1();
        __syncthreads();
        if (j + 2 < J) cpchunk(j + 2);
        CP_COMMIT();
        const uint32_t st = sb + (j % 3) * STAGE_M;
        compute32(st,      aoff, boff, acc);   // k sub-chunk 0 (halves 0..31)
        compute32(st + 64, aoff, boff, acc);   // k sub-chunk 1 (halves 32..63)
    }

    const int r4 = lane >> 2, c2 = 2 * (lane & 3);
#pragma unroll
    for (int mi = 0; mi < 2; mi++) {
#pragma unroll
        for (int ni = 0; ni < 8; ni++) {
            const int nrow = wm * 32 + mi * 16 + r4;
            const int ocol = wn * 64 + ni * 8 + c2;
            float* op = out + ((size_t)(b * Nn + n0 + nrow)) * DOUT + o0 + ocol;
            float2 lo = { acc[mi][ni][0] + bsm[ocol], acc[mi][ni][1] + bsm[ocol + 1] };
            *reinterpret_cast<float2*>(op) = lo;
            float2 hi = { acc[mi][ni][2] + bsm[ocol], acc[mi][ni][3] + bsm[ocol + 1] };
            *reinterpret_cast<float2*>(op + (size_t)8 * DOUT) = hi;
        }
    }
}

// ---------------------------------------------------------------------------
extern "C" void kernel_launch(void* const* d_in, const int* in_sizes, int n_in,
                              void* d_out, int out_size) {
    const float *node = nullptr, *rel = nullptr, *adj = nullptr,
                *W = nullptr, *bias = nullptr;
    for (int i = 0; i < n_in; i++) {
        const int s = in_sizes[i];
        if      (s == Bn * Nn * DE)      node = (const float*)d_in[i];
        else if (s == Bn * Rn * DR)      rel  = (const float*)d_in[i];
        else if (s == Bn * Rn * Nn * Nn) adj  = (const float*)d_in[i];
        else if (s == DOUT * INDIM)      W    = (const float*)d_in[i];
        else if (s == DOUT)              bias = (const float*)d_in[i];
    }
    cudaFuncSetAttribute(k_zc,   cudaFuncAttributeMaxDynamicSharedMemorySize, KZ_SMEM);
    cudaFuncSetAttribute(k_main, cudaFuncAttributeMaxDynamicSharedMemorySize, KM_SMEM);

    k_pre <<<160, 256>>>(node, W, rel);
    k_zc  <<<GEMMB + CONVB, 256, KZ_SMEM>>>(adj);
    k_main<<<dim3(4, 2, Bn), 256, KM_SMEM>>>(bias, (float*)d_out);
}

// round 10
// speedup vs baseline: 1.6793x; 1.0009x over previous
#include <cuda_runtime.h>
#include <cuda_bf16.h>
#include <cstdint>

#define Bn   16
#define Nn   512
#define Rn   10
#define DE   256
#define DR   64
#define DOUT 256
#define INDIM 3200
#define RELS  320

// bf16 scratch
__device__ __align__(16) __nv_bfloat16 g_A [(size_t)Bn * Rn * Nn * Nn];   // adj bf16
__device__ __align__(16) __nv_bfloat16 g_Zb[(size_t)Bn * Rn * DOUT * Nn]; // Zt bf16
__device__ __align__(16) __nv_bfloat16 g_N [(size_t)Bn * Nn * DE];        // node bf16
__device__ __align__(16) __nv_bfloat16 g_W [(size_t)DOUT * INDIM];        // W bf16
__device__ float g_V[Bn * Rn * DOUT];                                     // v fp32
__device__ float g_P[2 * (size_t)Bn * Nn * DOUT];                         // split-K partials

// ---- k_zc (fused Z-GEMM + adj conversion): k=32 stages, RS=40 halves ----
#define RSZ 40
#define TILE_Z  (128 * RSZ * 2)
#define STAGE_Z (2 * TILE_Z)
#define KZ_SMEM (3 * STAGE_Z + Rn * 128 * 4)
#define GEMMB 128
#define CONVB 320

// ---- k_main: CTA 256x128, warp 64x64, k=32 stages ----
#define RSM 40
#define TILE_A2 (256 * RSM * 2)     // 20480 B
#define TILE_B2 (128 * RSM * 2)     // 10240 B
#define STAGE_M (TILE_A2 + TILE_B2) // 30720 B
#define KM_SMEM (3 * STAGE_M + 256)

__device__ __forceinline__ uint32_t smem_u32(const void* p) {
    uint32_t a;
    asm("{ .reg .u64 t; cvta.to.shared.u64 t, %1; cvt.u32.u64 %0, t; }"
        : "=r"(a) : "l"(p));
    return a;
}

#define CP_ASYNC16(dst_u32, src) \
    asm volatile("cp.async.cg.shared.global [%0], [%1], 16;" \
                 :: "r"(dst_u32), "l"(src) : "memory")
#define CP_COMMIT() asm volatile("cp.async.commit_group;" ::: "memory")
#define CP_WAIT1()  asm volatile("cp.async.wait_group 1;" ::: "memory")

#define LDMX4(r0, r1, r2, r3, addr) \
    asm volatile("ldmatrix.sync.aligned.m8n8.x4.shared.b16 {%0,%1,%2,%3}, [%4];" \
                 : "=r"(r0), "=r"(r1), "=r"(r2), "=r"(r3) : "r"(addr))

__device__ __forceinline__ void mma16(float* c, const uint32_t* a,
                                      uint32_t b0, uint32_t b1) {
    asm volatile(
        "mma.sync.aligned.m16n8k16.row.col.f32.bf16.bf16.f32 "
        "{%0,%1,%2,%3}, {%4,%5,%6,%7}, {%8,%9}, {%0,%1,%2,%3};"
        : "+f"(c[0]), "+f"(c[1]), "+f"(c[2]), "+f"(c[3])
        : "r"(a[0]), "r"(a[1]), "r"(a[2]), "r"(a[3]), "r"(b0), "r"(b1));
}

// k=32 chunk, warp tile 32x64 (k_zc path)
__device__ __forceinline__ void compute32(uint32_t st,
                                          const uint32_t (&aoff)[2][2],
                                          const uint32_t (&boff)[4][2],
                                          float (&acc)[2][8][4]) {
    uint32_t a[2][2][4], bq[4][2][4];
#pragma unroll
    for (int mi = 0; mi < 2; mi++)
#pragma unroll
        for (int kk = 0; kk < 2; kk++)
            LDMX4(a[mi][kk][0], a[mi][kk][1], a[mi][kk][2], a[mi][kk][3],
                  st + aoff[mi][kk]);
#pragma unroll
    for (int nb = 0; nb < 4; nb++)
#pragma unroll
        for (int kk = 0; kk < 2; kk++)
            LDMX4(bq[nb][kk][0], bq[nb][kk][1], bq[nb][kk][2], bq[nb][kk][3],
                  st + boff[nb][kk]);
#pragma unroll
    for (int kk = 0; kk < 2; kk++)
#pragma unroll
        for (int mi = 0; mi < 2; mi++)
#pragma unroll
            for (int ni = 0; ni < 8; ni++) {
                const int nb = ni >> 1, odd = ni & 1;
                mma16(acc[mi][ni], a[mi][kk], bq[nb][kk][odd], bq[nb][kk][2 + odd]);
            }
}

// ---------------------------------------------------------------------------
// k_pre: node/W -> bf16, v[b][r][o] (fp32).  grid 1280 x 256.
// ---------------------------------------------------------------------------
__global__ void k_pre(const float* __restrict__ node, const float* __restrict__ W,
                      const float* __restrict__ rel) {
    const size_t stride = (size_t)gridDim.x * blockDim.x;
    const size_t t0 = (size_t)blockIdx.x * blockDim.x + threadIdx.x;

    const size_t nnode = (size_t)Bn * Nn * DE / 4;
    for (size_t i = t0; i < nnode; i += stride) {
        float4 v = reinterpret_cast<const float4*>(node)[i];
        __nv_bfloat162 p0 = __floats2bfloat162_rn(v.x, v.y);
        __nv_bfloat162 p1 = __floats2bfloat162_rn(v.z, v.w);
        uint2 u = { *reinterpret_cast<unsigned*>(&p0), *reinterpret_cast<unsigned*>(&p1) };
        reinterpret_cast<uint2*>(g_N)[i] = u;
    }
    const size_t nw = (size_t)DOUT * INDIM / 4;
    for (size_t i = t0; i < nw; i += stride) {
        float4 v = reinterpret_cast<const float4*>(W)[i];
        __nv_bfloat162 p0 = __floats2bfloat162_rn(v.x, v.y);
        __nv_bfloat162 p1 = __floats2bfloat162_rn(v.z, v.w);
        uint2 u = { *reinterpret_cast<unsigned*>(&p0), *reinterpret_cast<unsigned*>(&p1) };
        reinterpret_cast<uint2*>(g_W)[i] = u;
    }
    if (blockIdx.x < Bn * Rn) {
        const int br = blockIdx.x, r = br % Rn;
        const int o = threadIdx.x;
        const float* wr = W + (size_t)o * INDIM + r * RELS + DE;
        const float* rp = rel + (size_t)br * DR;
        float s = 0.f;
#pragma unroll
        for (int d = 0; d < DR; d++) s += rp[d] * wr[d];
        g_V[br * DOUT + o] = s;
    }
}

// ---------------------------------------------------------------------------
// k_zc: blocks [0,128): Z GEMM; blocks [128,448): adj fp32 -> bf16 stream.
// ---------------------------------------------------------------------------
__global__ __launch_bounds__(256, 2) void k_zc(const float* __restrict__ adj) {
    const int tid = threadIdx.x;

    if (blockIdx.x >= GEMMB) {
        const size_t stride = (size_t)CONVB * 256;
        const size_t nq = (size_t)Bn * Rn * Nn * Nn / 4;
        for (size_t i = (size_t)(blockIdx.x - GEMMB) * 256 + tid; i < nq; i += stride) {
            float4 v = reinterpret_cast<const float4*>(adj)[i];
            __nv_bfloat162 p0 = __floats2bfloat162_rn(v.x, v.y);
            __nv_bfloat162 p1 = __floats2bfloat162_rn(v.z, v.w);
            uint2 u = { *reinterpret_cast<unsigned*>(&p0), *reinterpret_cast<unsigned*>(&p1) };
            reinterpret_cast<uint2*>(g_A)[i] = u;
        }
        return;
    }

    extern __shared__ __align__(16) char smc[];
    const uint32_t sb = smem_u32(smc);
    float* vs = reinterpret_cast<float*>(smc + 3 * STAGE_Z);

    const int lane = tid & 31, warp = tid >> 5;
    const int wm = warp & 3, wn = warp >> 2;
    const int bid = blockIdx.x;
    const int b = bid >> 3, tt = bid & 7;
    const int mm0 = (tt & 3) * 128;
    const int o0  = (tt >> 2) * 128;

#pragma unroll
    for (int i = 0; i < 5; i++) {
        const int idx = i * 256 + tid;
        vs[idx] = g_V[(b * Rn + (idx >> 7)) * DOUT + o0 + (idx & 127)];
    }

    const int t8 = lane >> 3;
    const int rIn = (t8 & 1) * 8 + (lane & 7), kIn = (t8 >> 1) * 8;
    uint32_t aoff[2][2], boff[4][2];
#pragma unroll
    for (int mi = 0; mi < 2; mi++)
#pragma unroll
        for (int kk = 0; kk < 2; kk++)
            aoff[mi][kk] = ((wm * 32 + mi * 16 + rIn) * RSZ + kk * 16 + kIn) * 2;
#pragma unroll
    for (int nb = 0; nb < 4; nb++)
#pragma unroll
        for (int kk = 0; kk < 2; kk++)
            boff[nb][kk] = TILE_Z + ((wn * 64 + nb * 16 + rIn) * RSZ + kk * 16 + kIn) * 2;

    float acc[2][8][4];
#pragma unroll
    for (int mi = 0; mi < 2; mi++)
#pragma unroll
        for (int ni = 0; ni < 8; ni++)
#pragma unroll
            for (int q = 0; q < 4; q++) acc[mi][ni][q] = 0.f;

    auto cpchunk = [&](int j) {
        const int rj = j >> 3, kk = j & 7;
        const __nv_bfloat16* Ag = g_W + (size_t)o0 * INDIM + rj * RELS + kk * 32;
        const __nv_bfloat16* Bg = g_N + (size_t)(b * Nn + mm0) * DE + kk * 32;
        const uint32_t st = sb + (j % 3) * STAGE_Z;
#pragma unroll
        for (int q = 0; q < 2; q++) {
            const int idx = q * 256 + tid, r = idx >> 2, s = idx & 3;
            CP_ASYNC16(st + (r * RSZ + s * 8) * 2, Ag + (size_t)r * INDIM + s * 8);
            CP_ASYNC16(st + TILE_Z + (r * RSZ + s * 8) * 2, Bg + (size_t)r * DE + s * 8);
        }
    };

    cpchunk(0); CP_COMMIT();
    cpchunk(1); CP_COMMIT();

    const int J = Rn * 8;
    const int r4 = lane >> 2, c2 = 2 * (lane & 3);
    for (int j = 0; j < J; j++) {
        CP_WAIT1();
        __syncthreads();
        if (j + 2 < J) cpchunk(j + 2);
        CP_COMMIT();
        compute32(sb + (j % 3) * STAGE_Z, aoff, boff, acc);
        if ((j & 7) == 7) {
            const int r = j >> 3;
            __nv_bfloat16* zr = g_Zb + (size_t)(b * Rn + r) * (DOUT * Nn);
#pragma unroll
            for (int mi = 0; mi < 2; mi++) {
#pragma unroll
                for (int ni = 0; ni < 8; ni++) {
                    const int orow = wm * 32 + mi * 16 + r4;
                    const int mcol = wn * 64 + ni * 8 + c2;
                    __nv_bfloat16* zp = zr + (size_t)(o0 + orow) * Nn + mm0 + mcol;
                    const float v0 = vs[r * 128 + orow];
                    __nv_bfloat162 lo = __floats2bfloat162_rn(acc[mi][ni][0] + v0,
                                                              acc[mi][ni][1] + v0);
                    *reinterpret_cast<__nv_bfloat162*>(zp) = lo;
                    const float v1 = vs[r * 128 + orow + 8];
                    __nv_bfloat162 hi = __floats2bfloat162_rn(acc[mi][ni][2] + v1,
                                                              acc[mi][ni][3] + v1);
                    *reinterpret_cast<__nv_bfloat162*>(zp + (size_t)8 * Nn) = hi;
#pragma unroll
                    for (int q = 0; q < 4; q++) acc[mi][ni][q] = 0.f;
                }
            }
        }
    }
}

// ---------------------------------------------------------------------------
// k_main: split-K2.  CTA tile n 256 (M) x o 128 (N), 8 warps of 64x64.
// Each CTA: K-half = 5 relations x 512 = 2560 = 80 chunks of k=32.
// Partials (fp32) -> g_P[ks].  grid (2 n, 2 o, 16 b * 2 ks), 256 threads.
// ---------------------------------------------------------------------------
__global__ __launch_bounds__(256, 1) void k_main() {
    extern __shared__ __align__(16) char smc[];
    const uint32_t sb = smem_u32(smc);

    const int tid = threadIdx.x, lane = tid & 31, warp = tid >> 5;
    const int wm = warp & 3, wn = warp >> 2;   // warp tile (wm*64, wn*64)
    const int zz = blockIdx.z;
    const int b = zz & 15, ks = zz >> 4;
    const int n0 = blockIdx.x * 256, o0 = blockIdx.y * 128;
    const int rbase = ks * 5;

    const int t8 = lane >> 3;
    const int rIn = (t8 & 1) * 8 + (lane & 7), kIn = (t8 >> 1) * 8;
    uint32_t aoff[4][2], boff[4][2];
#pragma unroll
    for (int mi = 0; mi < 4; mi++)
#pragma unroll
        for (int kk = 0; kk < 2; kk++)
            aoff[mi][kk] = ((wm * 64 + mi * 16 + rIn) * RSM + kk * 16 + kIn) * 2;
#pragma unroll
    for (int nb = 0; nb < 4; nb++)
#pragma unroll
        for (int kk = 0; kk < 2; kk++)
            boff[nb][kk] = TILE_A2 + ((wn * 64 + nb * 16 + rIn) * RSM + kk * 16 + kIn) * 2;

    float acc[4][8][4];
#pragma unroll
    for (int mi = 0; mi < 4; mi++)
#pragma unroll
        for (int ni = 0; ni < 8; ni++)
#pragma unroll
            for (int q = 0; q < 4; q++) acc[mi][ni][q] = 0.f;

    auto cpchunk = [&](int j) {
        const int rj = rbase + (j >> 4), kk = j & 15;
        const __nv_bfloat16* Ag = g_A + ((size_t)(b * Rn + rj) * Nn + n0) * Nn + kk * 32;
        const __nv_bfloat16* Bg = g_Zb + ((size_t)(b * Rn + rj) * DOUT + o0) * Nn + kk * 32;
        const uint32_t st = sb + (j % 3) * STAGE_M;
        // A: 256 rows x 32 halves (4 x 16B per row) -> 1024 cp / 256 thr = 4
#pragma unroll
        for (int q = 0; q < 4; q++) {
            const int idx = q * 256 + tid, r = idx >> 2, s = idx & 3;
            CP_ASYNC16(st + (r * RSM + s * 8) * 2, Ag + (size_t)r * Nn + s * 8);
        }
        // B: 128 rows x 32 halves -> 512 cp / 256 thr = 2
#pragma unroll
        for (int q = 0; q < 2; q++) {
            const int idx = q * 256 + tid, r = idx >> 2, s = idx & 3;
            CP_ASYNC16(st + TILE_A2 + (r * RSM + s * 8) * 2, Bg + (size_t)r * Nn + s * 8);
        }
    };

    cpchunk(0); CP_COMMIT();
    cpchunk(1); CP_COMMIT();

    const int J = 80;
    for (int j = 0; j < J; j++) {
        CP_WAIT1();
        __syncthreads();
        if (j + 2 < J) cpchunk(j + 2);
        CP_COMMIT();
        const uint32_t st = sb + (j % 3) * STAGE_M;
        // 16 ldmatrix + 64 mma per warp
        uint32_t a[4][2][4], bq[4][2][4];
#pragma unroll
        for (int mi = 0; mi < 4; mi++)
#pragma unroll
            for (int kk = 0; kk < 2; kk++)
                LDMX4(a[mi][kk][0], a[mi][kk][1], a[mi][kk][2], a[mi][kk][3],
                      st + aoff[mi][kk]);
#pragma unroll
        for (int nb = 0; nb < 4; nb++)
#pragma unroll
            for (int kk = 0; kk < 2; kk++)
                LDMX4(bq[nb][kk][0], bq[nb][kk][1], bq[nb][kk][2], bq[nb][kk][3],
                      st + boff[nb][kk]);
#pragma unroll
        for (int kk = 0; kk < 2; kk++)
#pragma unroll
            for (int mi = 0; mi < 4; mi++)
#pragma unroll
                for (int ni = 0; ni < 8; ni++) {
                    const int nb = ni >> 1, odd = ni & 1;
                    mma16(acc[mi][ni], a[mi][kk], bq[nb][kk][odd], bq[nb][kk][2 + odd]);
                }
    }

    float* P = g_P + (size_t)ks * Bn * Nn * DOUT;
    const int r4 = lane >> 2, c2 = 2 * (lane & 3);
#pragma unroll
    for (int mi = 0; mi < 4; mi++) {
#pragma unroll
        for (int ni = 0; ni < 8; ni++) {
            const int nrow = wm * 64 + mi * 16 + r4;
            const int ocol = wn * 64 + ni * 8 + c2;
            float* op = P + ((size_t)(b * Nn + n0 + nrow)) * DOUT + o0 + ocol;
            float2 lo = { acc[mi][ni][0], acc[mi][ni][1] };
            *reinterpret_cast<float2*>(op) = lo;
            float2 hi = { acc[mi][ni][2], acc[mi][ni][3] };
            *reinterpret_cast<float2*>(op + (size_t)8 * DOUT) = hi;
        }
    }
}

// ---------------------------------------------------------------------------
// k_red: out = P0 + P1 + bias.  2M floats, float4 per thread.
// ---------------------------------------------------------------------------
__global__ void k_red(const float* __restrict__ bias, float* __restrict__ out) {
    const size_t i = (size_t)blockIdx.x * blockDim.x + threadIdx.x;  // float4 idx
    const size_t half = (size_t)Bn * Nn * DOUT / 4;
    float4 p0 = reinterpret_cast<const float4*>(g_P)[i];
    float4 p1 = reinterpret_cast<const float4*>(g_P)[i + half];
    float4 bb = reinterpret_cast<const float4*>(bias)[i & (DOUT / 4 - 1)];
    float4 v = { p0.x + p1.x + bb.x, p0.y + p1.y + bb.y,
                 p0.z + p1.z + bb.z, p0.w + p1.w + bb.w };
    reinterpret_cast<float4*>(out)[i] = v;
}

// ---------------------------------------------------------------------------
extern "C" void kernel_launch(void* const* d_in, const int* in_sizes, int n_in,
                              void* d_out, int out_size) {
    const float *node = nullptr, *rel = nullptr, *adj = nullptr,
                *W = nullptr, *bias = nullptr;
    for (int i = 0; i < n_in; i++) {
        const int s = in_sizes[i];
        if      (s == Bn * Nn * DE)      node = (const float*)d_in[i];
        else if (s == Bn * Rn * DR)      rel  = (const float*)d_in[i];
        else if (s == Bn * Rn * Nn * Nn) adj  = (const float*)d_in[i];
        else if (s == DOUT * INDIM)      W    = (const float*)d_in[i];
        else if (s == DOUT)              bias = (const float*)d_in[i];
    }
    cudaFuncSetAttribute(k_zc,   cudaFuncAttributeMaxDynamicSharedMemorySize, KZ_SMEM);
    cudaFuncSetAttribute(k_main, cudaFuncAttributeMaxDynamicSharedMemorySize, KM_SMEM);

    k_pre <<<1280, 256>>>(node, W, rel);
    k_zc  <<<GEMMB + CONVB, 256, KZ_SMEM>>>(adj);
    k_main<<<dim3(2, 2, Bn * 2), 256, KM_SMEM>>>();
    k_red <<<(Bn * Nn * DOUT / 4) / 256, 256>>>(bias, (float*)d_out);
}

// round 12
// speedup vs baseline: 1.6929x; 1.0081x over previous
#include <cuda_runtime.h>
#include <cuda_bf16.h>
#include <cstdint>

#define Bn   16
#define Nn   512
#define Rn   10
#define DE   256
#define DR   64
#define DOUT 256
#define INDIM 3200
#define RELS  320

// bf16 scratch
__device__ __align__(16) __nv_bfloat16 g_A [(size_t)Bn * Rn * Nn * Nn];   // adj bf16
__device__ __align__(16) __nv_bfloat16 g_Zb[(size_t)Bn * Rn * DOUT * Nn]; // Zt bf16
__device__ __align__(16) __nv_bfloat16 g_N [(size_t)Bn * Nn * DE];        // node bf16
__device__ __align__(16) __nv_bfloat16 g_W [(size_t)DOUT * INDIM];        // W bf16
__device__ float g_V[Bn * Rn * DOUT];                                     // v fp32
__device__ float g_P[2 * (size_t)Bn * Nn * DOUT];                         // split-K partials

// ---- k_zc (fused Z-GEMM + adj conversion): k=32 stages, RS=40 halves ----
#define RSZ 40
#define TILE_Z  (128 * RSZ * 2)
#define STAGE_Z (2 * TILE_Z)
#define KZ_SMEM (3 * STAGE_Z + Rn * 128 * 4)
#define GEMMB 128
#define CONVB 320

// ---- k_main: CTA 128x128, 4 warps of 64x64, k=32 3-stage ----
#define RSM 40
#define TILE_MA (128 * RSM * 2)     // 10240 B
#define STAGE_M (2 * TILE_MA)       // 20480 B
#define KM_SMEM (3 * STAGE_M)       // 61440 B

__device__ __forceinline__ uint32_t smem_u32(const void* p) {
    uint32_t a;
    asm("{ .reg .u64 t; cvta.to.shared.u64 t, %1; cvt.u32.u64 %0, t; }"
        : "=r"(a) : "l"(p));
    return a;
}

#define CP_ASYNC16(dst_u32, src) \
    asm volatile("cp.async.cg.shared.global [%0], [%1], 16;" \
                 :: "r"(dst_u32), "l"(src) : "memory")
#define CP_COMMIT() asm volatile("cp.async.commit_group;" ::: "memory")
#define CP_WAIT1()  asm volatile("cp.async.wait_group 1;" ::: "memory")

#define LDMX4(r0, r1, r2, r3, addr) \
    asm volatile("ldmatrix.sync.aligned.m8n8.x4.shared.b16 {%0,%1,%2,%3}, [%4];" \
                 : "=r"(r0), "=r"(r1), "=r"(r2), "=r"(r3) : "r"(addr))

__device__ __forceinline__ void mma16(float* c, const uint32_t* a,
                                      uint32_t b0, uint32_t b1) {
    asm volatile(
        "mma.sync.aligned.m16n8k16.row.col.f32.bf16.bf16.f32 "
        "{%0,%1,%2,%3}, {%4,%5,%6,%7}, {%8,%9}, {%0,%1,%2,%3};"
        : "+f"(c[0]), "+f"(c[1]), "+f"(c[2]), "+f"(c[3])
        : "r"(a[0]), "r"(a[1]), "r"(a[2]), "r"(a[3]), "r"(b0), "r"(b1));
}

// k=32 chunk, warp tile 32x64 (k_zc path)
__device__ __forceinline__ void compute32(uint32_t st,
                                          const uint32_t (&aoff)[2][2],
                                          const uint32_t (&boff)[4][2],
                                          float (&acc)[2][8][4]) {
    uint32_t a[2][2][4], bq[4][2][4];
#pragma unroll
    for (int mi = 0; mi < 2; mi++)
#pragma unroll
        for (int kk = 0; kk < 2; kk++)
            LDMX4(a[mi][kk][0], a[mi][kk][1], a[mi][kk][2], a[mi][kk][3],
                  st + aoff[mi][kk]);
#pragma unroll
    for (int nb = 0; nb < 4; nb++)
#pragma unroll
        for (int kk = 0; kk < 2; kk++)
            LDMX4(bq[nb][kk][0], bq[nb][kk][1], bq[nb][kk][2], bq[nb][kk][3],
                  st + boff[nb][kk]);
#pragma unroll
    for (int kk = 0; kk < 2; kk++)
#pragma unroll
        for (int mi = 0; mi < 2; mi++)
#pragma unroll
            for (int ni = 0; ni < 8; ni++) {
                const int nb = ni >> 1, odd = ni & 1;
                mma16(acc[mi][ni], a[mi][kk], bq[nb][kk][odd], bq[nb][kk][2 + odd]);
            }
}

// ---------------------------------------------------------------------------
// k_pre: node/W -> bf16, v[b][r][o] (fp32).  grid 1280 x 256.
// ---------------------------------------------------------------------------
__global__ void k_pre(const float* __restrict__ node, const float* __restrict__ W,
                      const float* __restrict__ rel) {
    const size_t stride = (size_t)gridDim.x * blockDim.x;
    const size_t t0 = (size_t)blockIdx.x * blockDim.x + threadIdx.x;

    const size_t nnode = (size_t)Bn * Nn * DE / 4;
    for (size_t i = t0; i < nnode; i += stride) {
        float4 v = reinterpret_cast<const float4*>(node)[i];
        __nv_bfloat162 p0 = __floats2bfloat162_rn(v.x, v.y);
        __nv_bfloat162 p1 = __floats2bfloat162_rn(v.z, v.w);
        uint2 u = { *reinterpret_cast<unsigned*>(&p0), *reinterpret_cast<unsigned*>(&p1) };
        reinterpret_cast<uint2*>(g_N)[i] = u;
    }
    const size_t nw = (size_t)DOUT * INDIM / 4;
    for (size_t i = t0; i < nw; i += stride) {
        float4 v = reinterpret_cast<const float4*>(W)[i];
        __nv_bfloat162 p0 = __floats2bfloat162_rn(v.x, v.y);
        __nv_bfloat162 p1 = __floats2bfloat162_rn(v.z, v.w);
        uint2 u = { *reinterpret_cast<unsigned*>(&p0), *reinterpret_cast<unsigned*>(&p1) };
        reinterpret_cast<uint2*>(g_W)[i] = u;
    }
    if (blockIdx.x < Bn * Rn) {
        const int br = blockIdx.x, r = br % Rn;
        const int o = threadIdx.x;
        const float* wr = W + (size_t)o * INDIM + r * RELS + DE;
        const float* rp = rel + (size_t)br * DR;
        float s = 0.f;
#pragma unroll
        for (int d = 0; d < DR; d++) s += rp[d] * wr[d];
        g_V[br * DOUT + o] = s;
    }
}

// ---------------------------------------------------------------------------
// k_zc: blocks [0,128): Z GEMM; blocks [128,448): adj fp32 -> bf16 stream.
// ---------------------------------------------------------------------------
__global__ __launch_bounds__(256, 2) void k_zc(const float* __restrict__ adj) {
    const int tid = threadIdx.x;

    if (blockIdx.x >= GEMMB) {
        const size_t stride = (size_t)CONVB * 256;
        const size_t nq = (size_t)Bn * Rn * Nn * Nn / 4;
        for (size_t i = (size_t)(blockIdx.x - GEMMB) * 256 + tid; i < nq; i += stride) {
            float4 v = reinterpret_cast<const float4*>(adj)[i];
            __nv_bfloat162 p0 = __floats2bfloat162_rn(v.x, v.y);
            __nv_bfloat162 p1 = __floats2bfloat162_rn(v.z, v.w);
            uint2 u = { *reinterpret_cast<unsigned*>(&p0), *reinterpret_cast<unsigned*>(&p1) };
            reinterpret_cast<uint2*>(g_A)[i] = u;
        }
        return;
    }

    extern __shared__ __align__(16) char smc[];
    const uint32_t sb = smem_u32(smc);
    float* vs = reinterpret_cast<float*>(smc + 3 * STAGE_Z);

    const int lane = tid & 31, warp = tid >> 5;
    const int wm = warp & 3, wn = warp >> 2;
    const int bid = blockIdx.x;
    const int b = bid >> 3, tt = bid & 7;
    const int mm0 = (tt & 3) * 128;
    const int o0  = (tt >> 2) * 128;

#pragma unroll
    for (int i = 0; i < 5; i++) {
        const int idx = i * 256 + tid;
        vs[idx] = g_V[(b * Rn + (idx >> 7)) * DOUT + o0 + (idx & 127)];
    }

    const int t8 = lane >> 3;
    const int rIn = (t8 & 1) * 8 + (lane & 7), kIn = (t8 >> 1) * 8;
    uint32_t aoff[2][2], boff[4][2];
#pragma unroll
    for (int mi = 0; mi < 2; mi++)
#pragma unroll
        for (int kk = 0; kk < 2; kk++)
            aoff[mi][kk] = ((wm * 32 + mi * 16 + rIn) * RSZ + kk * 16 + kIn) * 2;
#pragma unroll
    for (int nb = 0; nb < 4; nb++)
#pragma unroll
        for (int kk = 0; kk < 2; kk++)
            boff[nb][kk] = TILE_Z + ((wn * 64 + nb * 16 + rIn) * RSZ + kk * 16 + kIn) * 2;

    float acc[2][8][4];
#pragma unroll
    for (int mi = 0; mi < 2; mi++)
#pragma unroll
        for (int ni = 0; ni < 8; ni++)
#pragma unroll
            for (int q = 0; q < 4; q++) acc[mi][ni][q] = 0.f;

    auto cpchunk = [&](int j) {
        const int rj = j >> 3, kk = j & 7;
        const __nv_bfloat16* Ag = g_W + (size_t)o0 * INDIM + rj * RELS + kk * 32;
        const __nv_bfloat16* Bg = g_N + (size_t)(b * Nn + mm0) * DE + kk * 32;
        const uint32_t st = sb + (j % 3) * STAGE_Z;
#pragma unroll
        for (int q = 0; q < 2; q++) {
            const int idx = q * 256 + tid, r = idx >> 2, s = idx & 3;
            CP_ASYNC16(st + (r * RSZ + s * 8) * 2, Ag + (size_t)r * INDIM + s * 8);
            CP_ASYNC16(st + TILE_Z + (r * RSZ + s * 8) * 2, Bg + (size_t)r * DE + s * 8);
        }
    };

    cpchunk(0); CP_COMMIT();
    cpchunk(1); CP_COMMIT();

    const int J = Rn * 8;
    const int r4 = lane >> 2, c2 = 2 * (lane & 3);
    for (int j = 0; j < J; j++) {
        CP_WAIT1();
        __syncthreads();
        if (j + 2 < J) cpchunk(j + 2);
        CP_COMMIT();
        compute32(sb + (j % 3) * STAGE_Z, aoff, boff, acc);
        if ((j & 7) == 7) {
            const int r = j >> 3;
            __nv_bfloat16* zr = g_Zb + (size_t)(b * Rn + r) * (DOUT * Nn);
#pragma unroll
            for (int mi = 0; mi < 2; mi++) {
#pragma unroll
                for (int ni = 0; ni < 8; ni++) {
                    const int orow = wm * 32 + mi * 16 + r4;
                    const int mcol = wn * 64 + ni * 8 + c2;
                    __nv_bfloat16* zp = zr + (size_t)(o0 + orow) * Nn + mm0 + mcol;
                    const float v0 = vs[r * 128 + orow];
                    __nv_bfloat162 lo = __floats2bfloat162_rn(acc[mi][ni][0] + v0,
                                                              acc[mi][ni][1] + v0);
                    *reinterpret_cast<__nv_bfloat162*>(zp) = lo;
                    const float v1 = vs[r * 128 + orow + 8];
                    __nv_bfloat162 hi = __floats2bfloat162_rn(acc[mi][ni][2] + v1,
                                                              acc[mi][ni][3] + v1);
                    *reinterpret_cast<__nv_bfloat162*>(zp + (size_t)8 * Nn) = hi;
#pragma unroll
                    for (int q = 0; q < 4; q++) acc[mi][ni][q] = 0.f;
                }
            }
        }
    }
}

// ---------------------------------------------------------------------------
// k_main: split-K2.  CTA tile n 128 (M) x o 128 (N), 4 warps (2x2) of 64x64.
// Each CTA: K-half = 5 relations x 512 = 80 chunks of k=32.
// Partials (fp32) -> g_P[ks].  grid (4 n, 2 o, 16 b * 2 ks), 128 threads.
// 48KB smem + ~26K regs per CTA -> 2 CTAs/SM co-resident.
// ---------------------------------------------------------------------------
__global__ __launch_bounds__(128, 2) void k_main() {
    extern __shared__ __align__(16) char smc[];
    const uint32_t sb = smem_u32(smc);

    const int tid = threadIdx.x, lane = tid & 31, warp = tid >> 5;
    const int wm = warp & 1, wn = warp >> 1;   // warp tile (wm*64, wn*64)
    const int zz = blockIdx.z;
    const int b = zz & 15, ks = zz >> 4;
    const int n0 = blockIdx.x * 128, o0 = blockIdx.y * 128;
    const int rbase = ks * 5;

    const int t8 = lane >> 3;
    const int rIn = (t8 & 1) * 8 + (lane & 7), kIn = (t8 >> 1) * 8;
    uint32_t aoff[4][2], boff[4][2];
#pragma unroll
    for (int mi = 0; mi < 4; mi++)
#pragma unroll
        for (int kk = 0; kk < 2; kk++)
            aoff[mi][kk] = ((wm * 64 + mi * 16 + rIn) * RSM + kk * 16 + kIn) * 2;
#pragma unroll
    for (int nb = 0; nb < 4; nb++)
#pragma unroll
        for (int kk = 0; kk < 2; kk++)
            boff[nb][kk] = TILE_MA + ((wn * 64 + nb * 16 + rIn) * RSM + kk * 16 + kIn) * 2;

    float acc[4][8][4];
#pragma unroll
    for (int mi = 0; mi < 4; mi++)
#pragma unroll
        for (int ni = 0; ni < 8; ni++)
#pragma unroll
            for (int q = 0; q < 4; q++) acc[mi][ni][q] = 0.f;

    auto cpchunk = [&](int j) {
        const int rj = rbase + (j >> 4), kk = j & 15;
        const __nv_bfloat16* Ag = g_A + ((size_t)(b * Rn + rj) * Nn + n0) * Nn + kk * 32;
        const __nv_bfloat16* Bg = g_Zb + ((size_t)(b * Rn + rj) * DOUT + o0) * Nn + kk * 32;
        const uint32_t st = sb + (j % 3) * STAGE_M;
        // A: 128 rows x 4 x 16B = 512 cp / 128 thr = 4;  B same.
#pragma unroll
        for (int q = 0; q < 4; q++) {
            const int idx = q * 128 + tid, r = idx >> 2, s = idx & 3;
            CP_ASYNC16(st + (r * RSM + s * 8) * 2, Ag + (size_t)r * Nn + s * 8);
            CP_ASYNC16(st + TILE_MA + (r * RSM + s * 8) * 2, Bg + (size_t)r * Nn + s * 8);
        }
    };

    cpchunk(0); CP_COMMIT();
    cpchunk(1); CP_COMMIT();

    const int J = 80;
    for (int j = 0; j < J; j++) {
        CP_WAIT1();
        __syncthreads();
        if (j + 2 < J) cpchunk(j + 2);
        CP_COMMIT();
        const uint32_t st = sb + (j % 3) * STAGE_M;
        uint32_t a[4][2][4], bq[4][2][4];
#pragma unroll
        for (int mi = 0; mi < 4; mi++)
#pragma unroll
            for (int kk = 0; kk < 2; kk++)
                LDMX4(a[mi][kk][0], a[mi][kk][1], a[mi][kk][2], a[mi][kk][3],
                      st + aoff[mi][kk]);
#pragma unroll
        for (int nb = 0; nb < 4; nb++)
#pragma unroll
            for (int kk = 0; kk < 2; kk++)
                LDMX4(bq[nb][kk][0], bq[nb][kk][1], bq[nb][kk][2], bq[nb][kk][3],
                      st + boff[nb][kk]);
#pragma unroll
        for (int kk = 0; kk < 2; kk++)
#pragma unroll
            for (int mi = 0; mi < 4; mi++)
#pragma unroll
                for (int ni = 0; ni < 8; ni++) {
                    const int nb = ni >> 1, odd = ni & 1;
                    mma16(acc[mi][ni], a[mi][kk], bq[nb][kk][odd], bq[nb][kk][2 + odd]);
                }
    }

    float* P = g_P + (size_t)ks * Bn * Nn * DOUT;
    const int r4 = lane >> 2, c2 = 2 * (lane & 3);
#pragma unroll
    for (int mi = 0; mi < 4; mi++) {
#pragma unroll
        for (int ni = 0; ni < 8; ni++) {
            const int nrow = wm * 64 + mi * 16 + r4;
            const int ocol = wn * 64 + ni * 8 + c2;
            float* op = P + ((size_t)(b * Nn + n0 + nrow)) * DOUT + o0 + ocol;
            float2 lo = { acc[mi][ni][0], acc[mi][ni][1] };
            *reinterpret_cast<float2*>(op) = lo;
            float2 hi = { acc[mi][ni][2], acc[mi][ni][3] };
            *reinterpret_cast<float2*>(op + (size_t)8 * DOUT) = hi;
        }
    }
}

// ---------------------------------------------------------------------------
// k_red: out = P0 + P1 + bias.  float4 per thread.
// ---------------------------------------------------------------------------
__global__ void k_red(const float* __restrict__ bias, float* __restrict__ out) {
    const size_t i = (size_t)blockIdx.x * blockDim.x + threadIdx.x;
    const size_t half = (size_t)Bn * Nn * DOUT / 4;
    float4 p0 = reinterpret_cast<const float4*>(g_P)[i];
    float4 p1 = reinterpret_cast<const float4*>(g_P)[i + half];
    float4 bb = reinterpret_cast<const float4*>(bias)[i & (DOUT / 4 - 1)];
    float4 v = { p0.x + p1.x + bb.x, p0.y + p1.y + bb.y,
                 p0.z + p1.z + bb.z, p0.w + p1.w + bb.w };
    reinterpret_cast<float4*>(out)[i] = v;
}

// ---------------------------------------------------------------------------
extern "C" void kernel_launch(void* const* d_in, const int* in_sizes, int n_in,
                              void* d_out, int out_size) {
    const float *node = nullptr, *rel = nullptr, *adj = nullptr,
                *W = nullptr, *bias = nullptr;
    for (int i = 0; i < n_in; i++) {
        const int s = in_sizes[i];
        if      (s == Bn * Nn * DE)      node = (const float*)d_in[i];
        else if (s == Bn * Rn * DR)      rel  = (const float*)d_in[i];
        else if (s == Bn * Rn * Nn * Nn) adj  = (const float*)d_in[i];
        else if (s == DOUT * INDIM)      W    = (const float*)d_in[i];
        else if (s == DOUT)              bias = (const float*)d_in[i];
    }
    cudaFuncSetAttribute(k_zc,   cudaFuncAttributeMaxDynamicSharedMemorySize, KZ_SMEM);
    cudaFuncSetAttribute(k_main, cudaFuncAttributeMaxDynamicSharedMemorySize, KM_SMEM);

    k_pre <<<1280, 256>>>(node, W, rel);
    k_zc  <<<GEMMB + CONVB, 256, KZ_SMEM>>>(adj);
    k_main<<<dim3(4, 2, Bn * 2), 128, KM_SMEM>>>();
    k_red <<<(Bn * Nn * DOUT / 4) / 256, 256>>>(bias, (float*)d_out);
}